// round 5
// baseline (speedup 1.0000x reference)
#include <cuda_runtime.h>
#include <math.h>

#define SS   2048
#define BB   64
#define IIN  256
#define HHID 512
#define EEMB 256
#define BH   (BB * HHID)              // 32768
#define OUT_HT ((size_t)SS * BH)      // 67108864
#define OUT_MT (OUT_HT + BH)
#define GRID_C 128

// ---------------- device scratch ----------------
__device__ float g_Wc[HHID * HHID];   // Wc = Wm @ We   [H][H]
__device__ float g_bvec[HHID];        // b_ih + Wm @ b_embed
__device__ unsigned g_count = 0;
__device__ volatile unsigned g_gen = 0;

// ---------------- kernel A: prep Wc, bvec ----------------
__global__ __launch_bounds__(256) void prep_kernel(
    const float* __restrict__ W_ih, const float* __restrict__ W_embed,
    const float* __restrict__ b_ih, const float* __restrict__ b_embed)
{
    __shared__ float wm[EEMB];
    int h1 = blockIdx.x;              // 0..511
    int tid = threadIdx.x;            // 0..255
    wm[tid] = W_ih[(size_t)h1 * (IIN + EEMB) + IIN + tid];
    __syncthreads();

    float a0 = 0.f, a1 = 0.f;
    #pragma unroll 4
    for (int e = 0; e < EEMB; e++) {
        float w = wm[e];
        a0 = fmaf(w, W_embed[(size_t)e * HHID + tid],       a0);
        a1 = fmaf(w, W_embed[(size_t)e * HHID + tid + 256], a1);
    }
    g_Wc[(size_t)h1 * HHID + tid]       = a0;
    g_Wc[(size_t)h1 * HHID + tid + 256] = a1;

    if (tid == 0) {
        float s = b_ih[h1];
        for (int e = 0; e < EEMB; e++) s = fmaf(wm[e], b_embed[e], s);
        g_bvec[h1] = s;
    }
}

// ---------------- kernel B: P = X @ Wx^T (in-place into out) ----------------
// M = S*B = 131072, N = H = 512, K = I = 256. Tile 64x64, 256 thr, 4x4/thread.
__global__ __launch_bounds__(256) void gemm_p_kernel(
    const float* __restrict__ x, const float* __restrict__ W_ih,
    float* __restrict__ out)
{
    __shared__ float As[32][68];      // [k][m]
    __shared__ float Bs[32][68];      // [k][n]
    int tid = threadIdx.x;
    int n0 = blockIdx.x * 64;         // 8 blocks
    int m0 = blockIdx.y * 64;         // 2048 blocks
    int tx = tid & 15, ty = tid >> 4;

    float acc[4][4];
    #pragma unroll
    for (int i = 0; i < 4; i++)
        #pragma unroll
        for (int j = 0; j < 4; j++) acc[i][j] = 0.f;

    for (int k0 = 0; k0 < IIN; k0 += 32) {
        #pragma unroll
        for (int i = 0; i < 2; i++) {
            int f = tid + i * 256;    // 0..511
            int row = f >> 3;         // 0..63
            int kq  = (f & 7) << 2;   // 0..28
            float4 v = *reinterpret_cast<const float4*>(
                x + (size_t)(m0 + row) * IIN + k0 + kq);
            As[kq+0][row] = v.x; As[kq+1][row] = v.y;
            As[kq+2][row] = v.z; As[kq+3][row] = v.w;
            float4 w = *reinterpret_cast<const float4*>(
                W_ih + (size_t)(n0 + row) * (IIN + EEMB) + k0 + kq);
            Bs[kq+0][row] = w.x; Bs[kq+1][row] = w.y;
            Bs[kq+2][row] = w.z; Bs[kq+3][row] = w.w;
        }
        __syncthreads();
        #pragma unroll
        for (int k = 0; k < 32; k++) {
            float4 a = *reinterpret_cast<const float4*>(&As[k][ty * 4]);
            float4 b = *reinterpret_cast<const float4*>(&Bs[k][tx * 4]);
            float av[4] = {a.x, a.y, a.z, a.w};
            float bv[4] = {b.x, b.y, b.z, b.w};
            #pragma unroll
            for (int i = 0; i < 4; i++)
                #pragma unroll
                for (int j = 0; j < 4; j++)
                    acc[i][j] = fmaf(av[i], bv[j], acc[i][j]);
        }
        __syncthreads();
    }

    #pragma unroll
    for (int i = 0; i < 4; i++) {
        float4 v = make_float4(acc[i][0], acc[i][1], acc[i][2], acc[i][3]);
        *reinterpret_cast<float4*>(
            out + (size_t)(m0 + ty * 4 + i) * HHID + n0 + tx * 4) = v;
    }
}

// ---------------- kernel C: persistent recurrence ----------------
// 128 CTAs: bid&1 = chain (even/odd t), bid>>1 = 8-col block of H.
// Per iter: t = 2*it + chain; h[t] = tanh(P[t] + h[t-2] @ Wc^T + b')
// (t==0 uses m_0 @ Wm^T + b_ih; t==1 uses h_0 as h[-1].)

__device__ __forceinline__ void gemm_acc(
    const float* __restrict__ Ap, int stride, int K,
    const float* __restrict__ Bsq, float (*As)[68],
    int tid, int rp, int c, float& acc0, float& acc1)
{
    for (int k0 = 0; k0 < K; k0 += 64) {
        #pragma unroll
        for (int i = 0; i < 4; i++) {
            int f = tid + i * 256;    // 0..1023
            int row = f >> 4;         // 0..63
            int kq  = (f & 15) << 2;  // 0..60
            float4 v = __ldcg(reinterpret_cast<const float4*>(
                Ap + (size_t)row * stride + k0 + kq));
            *reinterpret_cast<float4*>(&As[row][kq]) = v;
        }
        __syncthreads();
        #pragma unroll
        for (int k4 = 0; k4 < 16; k4++) {
            float4 a0 = *reinterpret_cast<const float4*>(&As[rp][k4 * 4]);
            float4 a1 = *reinterpret_cast<const float4*>(&As[rp + 32][k4 * 4]);
            const float* bp = Bsq + (((k0 + k4 * 4) << 3) + c);
            float b0 = bp[0], b1 = bp[8], b2 = bp[16], b3 = bp[24];
            acc0 = fmaf(a0.x, b0, acc0); acc0 = fmaf(a0.y, b1, acc0);
            acc0 = fmaf(a0.z, b2, acc0); acc0 = fmaf(a0.w, b3, acc0);
            acc1 = fmaf(a1.x, b0, acc1); acc1 = fmaf(a1.y, b1, acc1);
            acc1 = fmaf(a1.z, b2, acc1); acc1 = fmaf(a1.w, b3, acc1);
        }
        __syncthreads();
    }
}

__global__ __launch_bounds__(256) void rnn_rec_kernel(
    const float* __restrict__ h0, const float* __restrict__ m0,
    const float* __restrict__ W_embed, const float* __restrict__ b_embed,
    const float* __restrict__ b_ih, const float* __restrict__ W_ih,
    float* __restrict__ out)
{
    __shared__ float Bsc[HHID * 8];   // Wc slice  [k][c]
    __shared__ float Bsm[EEMB * 8];   // Wm slice  [k][c]  (t==0 only)
    __shared__ float As[64][68];
    __shared__ float hs[HHID];        // epilogue

    int tid = threadIdx.x;
    int bid = blockIdx.x;
    int chain = bid & 1;
    int col0 = (bid >> 1) * 8;
    int c  = tid & 7;
    int rp = tid >> 3;                // 0..31
    int col = col0 + c;

    // resident weight slices (SMEM for all 1024 iterations)
    #pragma unroll
    for (int i = 0; i < 16; i++) {
        int j = tid + i * 256;        // 0..4095
        int cc = j >> 9, k = j & 511;
        Bsc[k * 8 + cc] = g_Wc[(size_t)(col0 + cc) * HHID + k];
    }
    #pragma unroll
    for (int i = 0; i < 8; i++) {
        int j = tid + i * 256;        // 0..2047
        int cc = j >> 8, k = j & 255;
        Bsm[k * 8 + cc] = W_ih[(size_t)(col0 + cc) * (IIN + EEMB) + IIN + k];
    }

    unsigned base = 0;
    if (tid == 0) base = g_gen;       // stable at launch (no barrier in flight)
    __syncthreads();

    float bias_v = g_bvec[col];
    float bih_v  = b_ih[col];

    for (int it = 0; it < 1024; it++) {
        int t = 2 * it + chain;
        const float* P = out + (size_t)t * BH;
        float acc0 = P[(size_t)rp * HHID + col];
        float acc1 = P[(size_t)(rp + 32) * HHID + col];

        if (t == 0) {
            acc0 += bih_v; acc1 += bih_v;
            gemm_acc(m0, EEMB, EEMB, Bsm, As, tid, rp, c, acc0, acc1);
        } else {
            acc0 += bias_v; acc1 += bias_v;
            const float* Ap = (t == 1) ? h0 : (out + (size_t)(t - 2) * BH);
            gemm_acc(Ap, HHID, HHID, Bsc, As, tid, rp, c, acc0, acc1);
        }

        out[(size_t)t * BH + (size_t)rp * HHID + col]        = tanhf(acc0);
        out[(size_t)t * BH + (size_t)(rp + 32) * HHID + col] = tanhf(acc1);

        // ---- grid barrier (generation counting, wrap-safe) ----
        __threadfence();
        __syncthreads();
        if (tid == 0) {
            unsigned want = (unsigned)it + 1u;
            if (atomicAdd(&g_count, 1u) == GRID_C - 1u) {
                atomicExch(&g_count, 0u);
                __threadfence();
                g_gen = base + want;
            } else {
                while ((unsigned)(g_gen - base) < want) { __nanosleep(32); }
                __threadfence();
            }
        }
        __syncthreads();
    }

    // ---- epilogue: m_T and h_T ----
    if (bid < 64) {
        // m_T row b = bid : m_T[b][e] = b_embed[e] + sum_h h[2046][b][h]*We[e][h]
        const float* hrow = out + (size_t)2046 * BH + (size_t)bid * HHID;
        hs[tid]       = __ldcg(hrow + tid);
        hs[tid + 256] = __ldcg(hrow + tid + 256);
        __syncthreads();
        float acc = b_embed[tid];                 // e = tid
        const float* we = W_embed + (size_t)tid * HHID;
        #pragma unroll 4
        for (int h = 0; h < HHID; h++) acc = fmaf(hs[h], we[h], acc);
        out[OUT_MT + (size_t)bid * EEMB + tid] = acc;
    } else {
        // h_T = outputs[2047] : 64 CTAs x 512 floats
        int j = (bid - 64) * 512 + tid;
        out[OUT_HT + j]       = __ldcg(out + (size_t)2047 * BH + j);
        out[OUT_HT + j + 256] = __ldcg(out + (size_t)2047 * BH + j + 256);
    }
}

// ---------------- launch ----------------
extern "C" void kernel_launch(void* const* d_in, const int* in_sizes, int n_in,
                              void* d_out, int out_size) {
    const float* input_seq = (const float*)d_in[0];
    const float* h_0       = (const float*)d_in[1];
    const float* m_0       = (const float*)d_in[2];
    const float* W_embed   = (const float*)d_in[3];
    const float* b_embed   = (const float*)d_in[4];
    const float* W_ih      = (const float*)d_in[5];
    const float* b_ih      = (const float*)d_in[6];
    float* out = (float*)d_out;

    prep_kernel<<<HHID, 256>>>(W_ih, W_embed, b_ih, b_embed);
    gemm_p_kernel<<<dim3(8, 2048), 256>>>(input_seq, W_ih, out);
    rnn_rec_kernel<<<GRID_C, 256>>>(h_0, m_0, W_embed, b_embed, b_ih, W_ih, out);
}

// round 6
// speedup vs baseline: 2.2856x; 2.2856x over previous
#include <cuda_runtime.h>
#include <cuda_bf16.h>
#include <math.h>

#define SS 2048
#define BB 64
#define IIN 256
#define HHID 512
#define EEMB 256
#define BH (BB*HHID)
#define OUT_HT ((size_t)SS*BH)
#define OUT_MT (OUT_HT+BH)
#define PITCH 520
// dyn smem: As1 66560 | As2 66560 | Bf1 16384 | Bf2 16384 = 165888
#define AS2_OFF 66560
#define BF1_OFF 133120
#define BF2_OFF 149504
#define REC_SMEM 165888

__device__ float g_Wc[HHID*HHID];
__device__ float g_bvec[HHID];
__device__ __nv_bfloat16 g_A1[2][2][BH];
__device__ __nv_bfloat16 g_A2[2][2][BH];
__device__ unsigned g_cnt[2] = {0,0};
__device__ volatile unsigned g_gen[2] = {0,0};

__device__ __forceinline__ void split2(float a,float b,unsigned&hi,unsigned&lo){
    __nv_bfloat16 ah=__float2bfloat16_rn(a), bh=__float2bfloat16_rn(b);
    __nv_bfloat162 H; H.x=ah; H.y=bh;
    __nv_bfloat162 L=__floats2bfloat162_rn(a-__bfloat162float(ah), b-__bfloat162float(bh));
    hi=*reinterpret_cast<unsigned*>(&H); lo=*reinterpret_cast<unsigned*>(&L);
}
__device__ __forceinline__ void mma4(float&d0,float&d1,float&d2,float&d3,
    unsigned a0,unsigned a1,unsigned a2,unsigned a3,unsigned b0,unsigned b1){
    asm volatile("mma.sync.aligned.m16n8k16.row.col.f32.bf16.bf16.f32 "
        "{%0,%1,%2,%3},{%4,%5,%6,%7},{%8,%9},{%0,%1,%2,%3};\n"
        :"+f"(d0),"+f"(d1),"+f"(d2),"+f"(d3)
        :"r"(a0),"r"(a1),"r"(a2),"r"(a3),"r"(b0),"r"(b1));
}

// ---- A: Wc = Wm@We, b' = b_ih + Wm@b_e ----
__global__ __launch_bounds__(256) void prep_kernel(
    const float* __restrict__ W_ih,const float* __restrict__ W_embed,
    const float* __restrict__ b_ih,const float* __restrict__ b_embed){
    __shared__ float wm[EEMB];
    int h1=blockIdx.x, tid=threadIdx.x;
    wm[tid]=W_ih[(size_t)h1*(IIN+EEMB)+IIN+tid];
    __syncthreads();
    float a0=0.f,a1=0.f;
    #pragma unroll 4
    for(int e=0;e<EEMB;e++){
        float w=wm[e];
        a0=fmaf(w,W_embed[(size_t)e*HHID+tid],a0);
        a1=fmaf(w,W_embed[(size_t)e*HHID+tid+256],a1);
    }
    g_Wc[(size_t)h1*HHID+tid]=a0;
    g_Wc[(size_t)h1*HHID+tid+256]=a1;
    if(tid==0){
        float s=b_ih[h1];
        for(int e=0;e<EEMB;e++) s=fmaf(wm[e],b_embed[e],s);
        g_bvec[h1]=s;
    }
}

// ---- B: P = X@Wx^T into out ----
__global__ __launch_bounds__(256) void gemm_p_kernel(
    const float* __restrict__ x,const float* __restrict__ W_ih,float* __restrict__ out){
    __shared__ float As[32][68];
    __shared__ float Bs[32][68];
    int tid=threadIdx.x, n0=blockIdx.x*64, m0=blockIdx.y*64;
    int tx=tid&15, ty=tid>>4;
    float acc[4][4];
    #pragma unroll
    for(int i=0;i<4;i++)
        #pragma unroll
        for(int j=0;j<4;j++) acc[i][j]=0.f;
    for(int k0=0;k0<IIN;k0+=32){
        #pragma unroll
        for(int i=0;i<2;i++){
            int f=tid+i*256, row=f>>3, kq=(f&7)<<2;
            float4 v=*reinterpret_cast<const float4*>(x+(size_t)(m0+row)*IIN+k0+kq);
            As[kq][row]=v.x;As[kq+1][row]=v.y;As[kq+2][row]=v.z;As[kq+3][row]=v.w;
            float4 w=*reinterpret_cast<const float4*>(W_ih+(size_t)(n0+row)*(IIN+EEMB)+k0+kq);
            Bs[kq][row]=w.x;Bs[kq+1][row]=w.y;Bs[kq+2][row]=w.z;Bs[kq+3][row]=w.w;
        }
        __syncthreads();
        #pragma unroll
        for(int k=0;k<32;k++){
            float4 a=*reinterpret_cast<const float4*>(&As[k][ty*4]);
            float4 b=*reinterpret_cast<const float4*>(&Bs[k][tx*4]);
            float av[4]={a.x,a.y,a.z,a.w}, bv[4]={b.x,b.y,b.z,b.w};
            #pragma unroll
            for(int i=0;i<4;i++)
                #pragma unroll
                for(int j=0;j<4;j++) acc[i][j]=fmaf(av[i],bv[j],acc[i][j]);
        }
        __syncthreads();
    }
    #pragma unroll
    for(int i=0;i<4;i++){
        float4 v=make_float4(acc[i][0],acc[i][1],acc[i][2],acc[i][3]);
        *reinterpret_cast<float4*>(out+(size_t)(m0+ty*4+i)*HHID+n0+tx*4)=v;
    }
}

// ---- boot: h[0]=tanh(P0+m0@Wm^T+b_ih); seed planes for both chains ----
__global__ __launch_bounds__(64) void boot_kernel(
    const float* __restrict__ h0,const float* __restrict__ m0,
    const float* __restrict__ W_ih,const float* __restrict__ b_ih,
    float* __restrict__ out){
    __shared__ float wm[EEMB];
    int h=blockIdx.x, b=threadIdx.x;
    for(int e=b;e<EEMB;e+=64) wm[e]=W_ih[(size_t)h*(IIN+EEMB)+IIN+e];
    __syncthreads();
    float acc=b_ih[h];
    const float* mr=m0+(size_t)b*EEMB;
    #pragma unroll 4
    for(int e=0;e<EEMB;e++) acc=fmaf(wm[e],mr[e],acc);
    int idx=b*HHID+h;
    float v=tanhf(out[idx]+acc);
    out[idx]=v;
    __nv_bfloat16 vh=__float2bfloat16_rn(v);
    g_A1[0][0][idx]=vh; g_A2[0][0][idx]=__float2bfloat16_rn(v-__bfloat162float(vh));
    float u=h0[idx];
    __nv_bfloat16 uh=__float2bfloat16_rn(u);
    g_A1[1][0][idx]=uh; g_A2[1][0][idx]=__float2bfloat16_rn(u-__bfloat162float(uh));
}

// ---- C: persistent recurrence, bf16x3 tensor ----
// 64 CTAs: bid&1=chain, (bid>>1)*16=col0. Chain0: t=2i+2 (1023 it); chain1: t=2i+1 (1024 it).
__global__ void __launch_bounds__(256,1) rnn_rec(float* __restrict__ out){
    extern __shared__ char smc[];
    __nv_bfloat16* As1=(__nv_bfloat16*)smc;
    __nv_bfloat16* As2=(__nv_bfloat16*)(smc+AS2_OFF);
    uint2* Bf1=(uint2*)(smc+BF1_OFF);
    uint2* Bf2=(uint2*)(smc+BF2_OFF);
    const int tid=threadIdx.x, bid=blockIdx.x;
    const int lane=tid&31, wid=tid>>5;
    const int chain=bid&1, col0=(bid>>1)*16;
    const int mtile=wid&3, nhalf=wid>>2;
    const int g=lane>>2, qi=lane&3;
    const int r0=mtile*16+g, cb=col0+nhalf*8+2*qi;

    // resident B fragments (Wc slice, hi+lo planes)
    for(int idx=tid;idx<2048;idx+=256){
        int nh=idx>>10, rem=idx&1023, ks=rem>>5, ln=rem&31;
        int n=col0+nh*8+(ln>>2), k=ks*16+(ln&3)*2;
        const float* wr=g_Wc+(size_t)n*HHID+k;
        unsigned h0v,l0v,h1v,l1v;
        split2(wr[0],wr[1],h0v,l0v);
        split2(wr[8],wr[9],h1v,l1v);
        Bf1[idx]=make_uint2(h0v,h1v);
        Bf2[idx]=make_uint2(l0v,l1v);
    }
    unsigned base=0;
    if(tid==0) base=g_gen[chain];
    __syncthreads();

    const float bias0=g_bvec[cb], bias1=g_bvec[cb+1];
    const int n_it=1023+chain;
    const __nv_bfloat16* a1p=As1+(size_t)r0*PITCH+qi*2;
    const __nv_bfloat16* a2p=As2+(size_t)r0*PITCH+qi*2;
    const uint2* b1p=Bf1+nhalf*1024+lane;
    const uint2* b2p=Bf2+nhalf*1024+lane;

    for(int i=0;i<n_it;i++){
        int t=2*i+2-chain;
        int rs=i&1, ws=rs^1;
        const __nv_bfloat16* pA1=g_A1[chain][rs];
        const __nv_bfloat16* pA2=g_A2[chain][rs];
        // stage A planes (coalesced 16B)
        #pragma unroll
        for(int j=0;j<16;j++){
            int f=tid+j*256, r=f>>6, c8=(f&63)*8;
            *reinterpret_cast<uint4*>(As1+r*PITCH+c8)=
                __ldcg(reinterpret_cast<const uint4*>(pA1+r*512+c8));
            *reinterpret_cast<uint4*>(As2+r*PITCH+c8)=
                __ldcg(reinterpret_cast<const uint4*>(pA2+r*512+c8));
        }
        __syncthreads();
        float c0=0.f,c1=0.f,c2=0.f,c3=0.f;
        #pragma unroll 8
        for(int ks=0;ks<32;ks++){
            int ko=ks*16;
            unsigned a0=*(const unsigned*)(a1p+ko);
            unsigned a1=*(const unsigned*)(a1p+8*PITCH+ko);
            unsigned a2=*(const unsigned*)(a1p+ko+8);
            unsigned a3=*(const unsigned*)(a1p+8*PITCH+ko+8);
            uint2 b1=b1p[ks*32], b2=b2p[ks*32];
            unsigned e0=*(const unsigned*)(a2p+ko);
            unsigned e1=*(const unsigned*)(a2p+8*PITCH+ko);
            unsigned e2=*(const unsigned*)(a2p+ko+8);
            unsigned e3=*(const unsigned*)(a2p+8*PITCH+ko+8);
            mma4(c0,c1,c2,c3,a0,a1,a2,a3,b1.x,b1.y);
            mma4(c0,c1,c2,c3,a0,a1,a2,a3,b2.x,b2.y);
            mma4(c0,c1,c2,c3,e0,e1,e2,e3,b1.x,b1.y);
        }
        // epilogue: add P + bias, tanh, write fp32 + planes
        {
            size_t o0=(size_t)t*BH+(size_t)r0*HHID+cb;
            size_t o1=o0+8*HHID;
            float2 p0=*reinterpret_cast<const float2*>(out+o0);
            float2 p1=*reinterpret_cast<const float2*>(out+o1);
            float v00=tanhf(p0.x+bias0+c0), v01=tanhf(p0.y+bias1+c1);
            float v10=tanhf(p1.x+bias0+c2), v11=tanhf(p1.y+bias1+c3);
            *reinterpret_cast<float2*>(out+o0)=make_float2(v00,v01);
            *reinterpret_cast<float2*>(out+o1)=make_float2(v10,v11);
            unsigned hi,lo;
            int q0=r0*HHID+cb, q1=q0+8*HHID;
            split2(v00,v01,hi,lo);
            *(unsigned*)(&g_A1[chain][ws][q0])=hi; *(unsigned*)(&g_A2[chain][ws][q0])=lo;
            split2(v10,v11,hi,lo);
            *(unsigned*)(&g_A1[chain][ws][q1])=hi; *(unsigned*)(&g_A2[chain][ws][q1])=lo;
        }
        // per-chain grid barrier (32 CTAs)
        __threadfence();
        __syncthreads();
        if(tid==0){
            unsigned want=base+(unsigned)i+1u;
            if(atomicAdd(&g_cnt[chain],1u)==31u){
                atomicExch(&g_cnt[chain],0u);
                __threadfence();
                g_gen[chain]=want;
            } else {
                while((unsigned)(g_gen[chain]-base)<(unsigned)(i+1)){ }
            }
            __threadfence();
        }
        __syncthreads();
    }
}

// ---- fin: m_T = h[2046]@We^T + b_e ; h_T = out[2047] ----
__global__ __launch_bounds__(256) void fin_kernel(
    const float* __restrict__ W_embed,const float* __restrict__ b_embed,
    float* __restrict__ out){
    __shared__ float hsr[HHID];
    int b=blockIdx.x, e=threadIdx.x;
    hsr[e]=out[(size_t)2046*BH+(size_t)b*HHID+e];
    hsr[e+256]=out[(size_t)2046*BH+(size_t)b*HHID+e+256];
    out[OUT_HT+(size_t)b*HHID+e]=out[(size_t)2047*BH+(size_t)b*HHID+e];
    out[OUT_HT+(size_t)b*HHID+e+256]=out[(size_t)2047*BH+(size_t)b*HHID+e+256];
    __syncthreads();
    float acc=b_embed[e];
    const float* we=W_embed+(size_t)e*HHID;
    #pragma unroll 4
    for(int h=0;h<HHID;h++) acc=fmaf(hsr[h],we[h],acc);
    out[OUT_MT+(size_t)b*EEMB+e]=acc;
}

extern "C" void kernel_launch(void* const* d_in,const int* in_sizes,int n_in,
                              void* d_out,int out_size){
    const float* input_seq=(const float*)d_in[0];
    const float* h_0=(const float*)d_in[1];
    const float* m_0=(const float*)d_in[2];
    const float* W_embed=(const float*)d_in[3];
    const float* b_embed=(const float*)d_in[4];
    const float* W_ih=(const float*)d_in[5];
    const float* b_ih=(const float*)d_in[6];
    float* out=(float*)d_out;

    cudaFuncSetAttribute(rnn_rec,cudaFuncAttributeMaxDynamicSharedMemorySize,REC_SMEM);
    prep_kernel<<<HHID,256>>>(W_ih,W_embed,b_ih,b_embed);
    gemm_p_kernel<<<dim3(8,2048),256>>>(input_seq,W_ih,out);
    boot_kernel<<<HHID,64>>>(h_0,m_0,W_ih,b_ih,out);
    rnn_rec<<<64,256,REC_SMEM>>>(out);
    fin_kernel<<<BB,256>>>(W_embed,b_embed,out);
}

// round 7
// speedup vs baseline: 2.8057x; 1.2276x over previous
#include <cuda_runtime.h>
#include <cuda_bf16.h>
#include <math.h>

#define SS 2048
#define BB 64
#define IIN 256
#define HHID 512
#define EEMB 256
#define BH (BB*HHID)
#define OUT_HT ((size_t)SS*BH)
#define OUT_MT (OUT_HT+BH)
#define PITCH 520
#define AS2_OFF 66560
#define BF1_OFF 133120
#define BF2_OFF 149504
#define REC_SMEM 165888

__device__ float g_Wc[HHID*HHID];
__device__ float g_bvec[HHID];
__device__ __nv_bfloat16 g_A1[2][2][BH];
__device__ __nv_bfloat16 g_A2[2][2][BH];
__device__ unsigned g_flag[2][32*32];   // [chain][cta*32] padded flags

__device__ __forceinline__ void split2(float a,float b,unsigned&hi,unsigned&lo){
    __nv_bfloat16 ah=__float2bfloat16_rn(a), bh=__float2bfloat16_rn(b);
    __nv_bfloat162 H; H.x=ah; H.y=bh;
    __nv_bfloat162 L=__floats2bfloat162_rn(a-__bfloat162float(ah), b-__bfloat162float(bh));
    hi=*reinterpret_cast<unsigned*>(&H); lo=*reinterpret_cast<unsigned*>(&L);
}
__device__ __forceinline__ void mma4(float&d0,float&d1,float&d2,float&d3,
    unsigned a0,unsigned a1,unsigned a2,unsigned a3,unsigned b0,unsigned b1){
    asm volatile("mma.sync.aligned.m16n8k16.row.col.f32.bf16.bf16.f32 "
        "{%0,%1,%2,%3},{%4,%5,%6,%7},{%8,%9},{%0,%1,%2,%3};\n"
        :"+f"(d0),"+f"(d1),"+f"(d2),"+f"(d3)
        :"r"(a0),"r"(a1),"r"(a2),"r"(a3),"r"(b0),"r"(b1));
}
__device__ __forceinline__ void ldsm4(unsigned&r0,unsigned&r1,unsigned&r2,unsigned&r3,unsigned a){
    asm volatile("ldmatrix.sync.aligned.m8n8.x4.shared.b16 {%0,%1,%2,%3},[%4];"
        :"=r"(r0),"=r"(r1),"=r"(r2),"=r"(r3):"r"(a));
}
__device__ __forceinline__ void cpa(unsigned s,const void*g){
    asm volatile("cp.async.cg.shared.global [%0],[%1],16;"::"r"(s),"l"(g):"memory");
}
__device__ __forceinline__ unsigned smem_u32(const void*p){
    unsigned a; asm("{.reg .u64 t; cvta.to.shared.u64 t,%1; cvt.u32.u64 %0,t;}":"=r"(a):"l"(p));
    return a;
}
__device__ __forceinline__ void st_flag(unsigned*p,unsigned v){
    asm volatile("st.global.relaxed.gpu.u32 [%0],%1;"::"l"(p),"r"(v):"memory");
}
__device__ __forceinline__ unsigned ld_flag(const unsigned*p){
    unsigned v; asm volatile("ld.global.acquire.gpu.u32 %0,[%1];":"=r"(v):"l"(p):"memory");
    return v;
}

// ---- A: Wc = Wm@We, b' = b_ih + Wm@b_e ----
__global__ __launch_bounds__(256) void prep_kernel(
    const float* __restrict__ W_ih,const float* __restrict__ W_embed,
    const float* __restrict__ b_ih,const float* __restrict__ b_embed){
    __shared__ float wm[EEMB];
    int h1=blockIdx.x, tid=threadIdx.x;
    wm[tid]=W_ih[(size_t)h1*(IIN+EEMB)+IIN+tid];
    __syncthreads();
    float a0=0.f,a1=0.f;
    #pragma unroll 4
    for(int e=0;e<EEMB;e++){
        float w=wm[e];
        a0=fmaf(w,W_embed[(size_t)e*HHID+tid],a0);
        a1=fmaf(w,W_embed[(size_t)e*HHID+tid+256],a1);
    }
    g_Wc[(size_t)h1*HHID+tid]=a0;
    g_Wc[(size_t)h1*HHID+tid+256]=a1;
    if(tid==0){
        float s=b_ih[h1];
        for(int e=0;e<EEMB;e++) s=fmaf(wm[e],b_embed[e],s);
        g_bvec[h1]=s;
    }
}

// ---- B: P = X@Wx^T into out ----
__global__ __launch_bounds__(256) void gemm_p_kernel(
    const float* __restrict__ x,const float* __restrict__ W_ih,float* __restrict__ out){
    __shared__ float As[32][68];
    __shared__ float Bs[32][68];
    int tid=threadIdx.x, n0=blockIdx.x*64, m0=blockIdx.y*64;
    int tx=tid&15, ty=tid>>4;
    float acc[4][4];
    #pragma unroll
    for(int i=0;i<4;i++)
        #pragma unroll
        for(int j=0;j<4;j++) acc[i][j]=0.f;
    for(int k0=0;k0<IIN;k0+=32){
        #pragma unroll
        for(int i=0;i<2;i++){
            int f=tid+i*256, row=f>>3, kq=(f&7)<<2;
            float4 v=*reinterpret_cast<const float4*>(x+(size_t)(m0+row)*IIN+k0+kq);
            As[kq][row]=v.x;As[kq+1][row]=v.y;As[kq+2][row]=v.z;As[kq+3][row]=v.w;
            float4 w=*reinterpret_cast<const float4*>(W_ih+(size_t)(n0+row)*(IIN+EEMB)+k0+kq);
            Bs[kq][row]=w.x;Bs[kq+1][row]=w.y;Bs[kq+2][row]=w.z;Bs[kq+3][row]=w.w;
        }
        __syncthreads();
        #pragma unroll
        for(int k=0;k<32;k++){
            float4 a=*reinterpret_cast<const float4*>(&As[k][ty*4]);
            float4 b=*reinterpret_cast<const float4*>(&Bs[k][tx*4]);
            float av[4]={a.x,a.y,a.z,a.w}, bv[4]={b.x,b.y,b.z,b.w};
            #pragma unroll
            for(int i=0;i<4;i++)
                #pragma unroll
                for(int j=0;j<4;j++) acc[i][j]=fmaf(av[i],bv[j],acc[i][j]);
        }
        __syncthreads();
    }
    #pragma unroll
    for(int i=0;i<4;i++){
        float4 v=make_float4(acc[i][0],acc[i][1],acc[i][2],acc[i][3]);
        *reinterpret_cast<float4*>(out+(size_t)(m0+ty*4+i)*HHID+n0+tx*4)=v;
    }
}

// ---- boot: h[0]=tanh(P0+m0@Wm^T+b_ih); seed planes; reset flags ----
__global__ __launch_bounds__(64) void boot_kernel(
    const float* __restrict__ h0,const float* __restrict__ m0,
    const float* __restrict__ W_ih,const float* __restrict__ b_ih,
    float* __restrict__ out){
    __shared__ float wm[EEMB];
    int h=blockIdx.x, b=threadIdx.x;
    if(h==0){ g_flag[0][b>=32? (b-32)*32:b*32]=0; g_flag[1][(b&31)*32]=0;
              g_flag[0][(b&31)*32]=0; }
    for(int e=b;e<EEMB;e+=64) wm[e]=W_ih[(size_t)h*(IIN+EEMB)+IIN+e];
    __syncthreads();
    float acc=b_ih[h];
    const float* mr=m0+(size_t)b*EEMB;
    #pragma unroll 4
    for(int e=0;e<EEMB;e++) acc=fmaf(wm[e],mr[e],acc);
    int idx=b*HHID+h;
    float v=tanhf(out[idx]+acc);
    out[idx]=v;
    __nv_bfloat16 vh=__float2bfloat16_rn(v);
    g_A1[0][0][idx]=vh; g_A2[0][0][idx]=__float2bfloat16_rn(v-__bfloat162float(vh));
    float u=h0[idx];
    __nv_bfloat16 uh=__float2bfloat16_rn(u);
    g_A1[1][0][idx]=uh; g_A2[1][0][idx]=__float2bfloat16_rn(u-__bfloat162float(uh));
}

// ---- C: persistent recurrence; ldmatrix + cp.async pipeline + flag barrier ----
__global__ void __launch_bounds__(256,1) rnn_rec(float* __restrict__ out){
    extern __shared__ char smc[];
    __nv_bfloat16* As1=(__nv_bfloat16*)smc;
    __nv_bfloat16* As2=(__nv_bfloat16*)(smc+AS2_OFF);
    uint2* Bf1=(uint2*)(smc+BF1_OFF);
    uint2* Bf2=(uint2*)(smc+BF2_OFF);
    const int tid=threadIdx.x, bid=blockIdx.x;
    const int lane=tid&31, wid=tid>>5;
    const int chain=bid&1, cta=bid>>1, col0=cta*16;
    const int mtile=wid&3, nhalf=wid>>2;
    const int g=lane>>2, qi=lane&3;
    const int r0=mtile*16+g, cb=col0+nhalf*8+2*qi;

    // resident B fragments (Wc slice, hi+lo planes)
    for(int idx=tid;idx<2048;idx+=256){
        int nh=idx>>10, rem=idx&1023, ks=rem>>5, ln=rem&31;
        int n=col0+nh*8+(ln>>2), k=ks*16+(ln&3)*2;
        const float* wr=g_Wc+(size_t)n*HHID+k;
        unsigned h0v,l0v,h1v,l1v;
        split2(wr[0],wr[1],h0v,l0v);
        split2(wr[8],wr[9],h1v,l1v);
        Bf1[idx]=make_uint2(h0v,h1v);
        Bf2[idx]=make_uint2(l0v,l1v);
    }
    const float bias0=g_bvec[cb], bias1=g_bvec[cb+1];
    const int n_it=1023+chain;
    // ldmatrix per-lane addresses
    const unsigned as1u=smem_u32(As1), as2u=smem_u32(As2);
    const int lrow=mtile*16+(lane&7)+(lane&8);
    const int lcol=(lane&16)>>1;
    const unsigned a1a=as1u+(unsigned)(lrow*PITCH+lcol)*2u;
    const unsigned a2a=as2u+(unsigned)(lrow*PITCH+lcol)*2u;
    const uint2* b1p=Bf1+nhalf*1024+lane;
    const uint2* b2p=Bf2+nhalf*1024+lane;
    __syncthreads();

    for(int i=0;i<n_it;i++){
        int t=2*i+2-chain;
        int rs=i&1, ws=rs^1;
        const __nv_bfloat16* pA1=g_A1[chain][rs];
        const __nv_bfloat16* pA2=g_A2[chain][rs];
        // stage half0 then half1 (async groups)
        #pragma unroll
        for(int j=0;j<8;j++){
            int f=tid+j*256, r=f>>5, c=(f&31)*8;
            cpa(as1u+(unsigned)(r*PITCH+c)*2u, pA1+r*512+c);
            cpa(as2u+(unsigned)(r*PITCH+c)*2u, pA2+r*512+c);
        }
        asm volatile("cp.async.commit_group;":::"memory");
        #pragma unroll
        for(int j=0;j<8;j++){
            int f=tid+j*256, r=f>>5, c=(f&31)*8+256;
            cpa(as1u+(unsigned)(r*PITCH+c)*2u, pA1+r*512+c);
            cpa(as2u+(unsigned)(r*PITCH+c)*2u, pA2+r*512+c);
        }
        asm volatile("cp.async.commit_group;":::"memory");
        // P loads early (independent)
        size_t o0=(size_t)t*BH+(size_t)r0*HHID+cb, o1=o0+8*HHID;
        float2 p0=__ldcg(reinterpret_cast<const float2*>(out+o0));
        float2 p1=__ldcg(reinterpret_cast<const float2*>(out+o1));
        float c0=0.f,c1=0.f,c2=0.f,c3=0.f;
        asm volatile("cp.async.wait_group 1;":::"memory");
        __syncthreads();
        #pragma unroll
        for(int ks=0;ks<16;ks++){
            unsigned x0,x1,x2,x3,y0,y1,y2,y3;
            ldsm4(x0,x1,x2,x3, a1a+(unsigned)(ks*32));
            ldsm4(y0,y1,y2,y3, a2a+(unsigned)(ks*32));
            uint2 b1=b1p[ks*32], b2=b2p[ks*32];
            mma4(c0,c1,c2,c3, x0,x1,x2,x3, b1.x,b1.y);
            mma4(c0,c1,c2,c3, x0,x1,x2,x3, b2.x,b2.y);
            mma4(c0,c1,c2,c3, y0,y1,y2,y3, b1.x,b1.y);
        }
        asm volatile("cp.async.wait_group 0;":::"memory");
        __syncthreads();
        #pragma unroll
        for(int ks=16;ks<32;ks++){
            unsigned x0,x1,x2,x3,y0,y1,y2,y3;
            ldsm4(x0,x1,x2,x3, a1a+(unsigned)(ks*32));
            ldsm4(y0,y1,y2,y3, a2a+(unsigned)(ks*32));
            uint2 b1=b1p[ks*32], b2=b2p[ks*32];
            mma4(c0,c1,c2,c3, x0,x1,x2,x3, b1.x,b1.y);
            mma4(c0,c1,c2,c3, x0,x1,x2,x3, b2.x,b2.y);
            mma4(c0,c1,c2,c3, y0,y1,y2,y3, b1.x,b1.y);
        }
        // epilogue
        {
            float v00=tanhf(p0.x+bias0+c0), v01=tanhf(p0.y+bias1+c1);
            float v10=tanhf(p1.x+bias0+c2), v11=tanhf(p1.y+bias1+c3);
            *reinterpret_cast<float2*>(out+o0)=make_float2(v00,v01);
            *reinterpret_cast<float2*>(out+o1)=make_float2(v10,v11);
            unsigned hi,lo;
            int q0=r0*HHID+cb, q1=q0+8*HHID;
            split2(v00,v01,hi,lo);
            *(unsigned*)(&g_A1[chain][ws][q0])=hi; *(unsigned*)(&g_A2[chain][ws][q0])=lo;
            split2(v10,v11,hi,lo);
            *(unsigned*)(&g_A1[chain][ws][q1])=hi; *(unsigned*)(&g_A2[chain][ws][q1])=lo;
        }
        // barrier: arrive (flag) + poll 32 flags in warp 0
        __syncthreads();
        if(tid==0){ __threadfence(); st_flag(&g_flag[chain][cta*32],(unsigned)(i+1)); }
        if(wid==0){
            const unsigned* fp=&g_flag[chain][lane*32];
            unsigned v;
            do { v=ld_flag(fp); } while(!__all_sync(0xffffffffu, v>(unsigned)i));
        }
        __syncthreads();
    }
}

// ---- fin: m_T = h[2046]@We^T + b_e ; h_T = out[2047] ----
__global__ __launch_bounds__(256) void fin_kernel(
    const float* __restrict__ W_embed,const float* __restrict__ b_embed,
    float* __restrict__ out){
    __shared__ float hsr[HHID];
    int b=blockIdx.x, e=threadIdx.x;
    hsr[e]=out[(size_t)2046*BH+(size_t)b*HHID+e];
    hsr[e+256]=out[(size_t)2046*BH+(size_t)b*HHID+e+256];
    out[OUT_HT+(size_t)b*HHID+e]=out[(size_t)2047*BH+(size_t)b*HHID+e];
    out[OUT_HT+(size_t)b*HHID+e+256]=out[(size_t)2047*BH+(size_t)b*HHID+e+256];
    __syncthreads();
    float acc=b_embed[e];
    const float* we=W_embed+(size_t)e*HHID;
    #pragma unroll 4
    for(int h=0;h<HHID;h++) acc=fmaf(hsr[h],we[h],acc);
    out[OUT_MT+(size_t)b*EEMB+e]=acc;
}

extern "C" void kernel_launch(void* const* d_in,const int* in_sizes,int n_in,
                              void* d_out,int out_size){
    const float* input_seq=(const float*)d_in[0];
    const float* h_0=(const float*)d_in[1];
    const float* m_0=(const float*)d_in[2];
    const float* W_embed=(const float*)d_in[3];
    const float* b_embed=(const float*)d_in[4];
    const float* W_ih=(const float*)d_in[5];
    const float* b_ih=(const float*)d_in[6];
    float* out=(float*)d_out;

    cudaFuncSetAttribute(rnn_rec,cudaFuncAttributeMaxDynamicSharedMemorySize,REC_SMEM);
    prep_kernel<<<HHID,256>>>(W_ih,W_embed,b_ih,b_embed);
    gemm_p_kernel<<<dim3(8,2048),256>>>(input_seq,W_ih,out);
    boot_kernel<<<HHID,64>>>(h_0,m_0,W_ih,b_ih,out);
    rnn_rec<<<64,256,REC_SMEM>>>(out);
    fin_kernel<<<BB,256>>>(W_embed,b_embed,out);
}

// round 8
// speedup vs baseline: 2.8446x; 1.0139x over previous
#include <cuda_runtime.h>
#include <cuda_bf16.h>
#include <math.h>

#define SS 2048
#define BB 64
#define IIN 256
#define HHID 512
#define EEMB 256
#define BH (BB*HHID)
#define OUT_HT ((size_t)SS*BH)
#define OUT_MT (OUT_HT+BH)
#define REC_SMEM 65536

__device__ float g_Wc[HHID*HHID];
__device__ float g_bvec[HHID];
// h planes in MMA-fragment layout: [chain][slot][mtile*1024 + ks*32 + lane]
__device__ uint4 g_F1[2][2][4096];   // hi plane
__device__ uint4 g_F2[2][2][4096];   // residual plane
__device__ unsigned g_flag[2][16*32];

__device__ __forceinline__ void split2(float a,float b,unsigned&hi,unsigned&lo){
    __nv_bfloat16 ah=__float2bfloat16_rn(a), bh=__float2bfloat16_rn(b);
    __nv_bfloat162 H; H.x=ah; H.y=bh;
    __nv_bfloat162 L=__floats2bfloat162_rn(a-__bfloat162float(ah), b-__bfloat162float(bh));
    hi=*reinterpret_cast<unsigned*>(&H); lo=*reinterpret_cast<unsigned*>(&L);
}
__device__ __forceinline__ void mma4(float&d0,float&d1,float&d2,float&d3,
    unsigned a0,unsigned a1,unsigned a2,unsigned a3,unsigned b0,unsigned b1){
    asm volatile("mma.sync.aligned.m16n8k16.row.col.f32.bf16.bf16.f32 "
        "{%0,%1,%2,%3},{%4,%5,%6,%7},{%8,%9},{%0,%1,%2,%3};\n"
        :"+f"(d0),"+f"(d1),"+f"(d2),"+f"(d3)
        :"r"(a0),"r"(a1),"r"(a2),"r"(a3),"r"(b0),"r"(b1));
}
__device__ __forceinline__ void st_flag(unsigned*p,unsigned v){
    asm volatile("st.global.relaxed.gpu.u32 [%0],%1;"::"l"(p),"r"(v):"memory");
}
__device__ __forceinline__ unsigned ld_flag(const unsigned*p){
    unsigned v; asm volatile("ld.global.acquire.gpu.u32 %0,[%1];":"=r"(v):"l"(p):"memory");
    return v;
}

// ---- A: Wc = Wm@We, b' = b_ih + Wm@b_e ----
__global__ __launch_bounds__(256) void prep_kernel(
    const float* __restrict__ W_ih,const float* __restrict__ W_embed,
    const float* __restrict__ b_ih,const float* __restrict__ b_embed){
    __shared__ float wm[EEMB];
    int h1=blockIdx.x, tid=threadIdx.x;
    wm[tid]=W_ih[(size_t)h1*(IIN+EEMB)+IIN+tid];
    __syncthreads();
    float a0=0.f,a1=0.f;
    #pragma unroll 4
    for(int e=0;e<EEMB;e++){
        float w=wm[e];
        a0=fmaf(w,W_embed[(size_t)e*HHID+tid],a0);
        a1=fmaf(w,W_embed[(size_t)e*HHID+tid+256],a1);
    }
    g_Wc[(size_t)h1*HHID+tid]=a0;
    g_Wc[(size_t)h1*HHID+tid+256]=a1;
    if(tid==0){
        float s=b_ih[h1];
        for(int e=0;e<EEMB;e++) s=fmaf(wm[e],b_embed[e],s);
        g_bvec[h1]=s;
    }
}

// ---- B: P = X@Wx^T into out ----
__global__ __launch_bounds__(256) void gemm_p_kernel(
    const float* __restrict__ x,const float* __restrict__ W_ih,float* __restrict__ out){
    __shared__ float As[32][68];
    __shared__ float Bs[32][68];
    int tid=threadIdx.x, n0=blockIdx.x*64, m0=blockIdx.y*64;
    int tx=tid&15, ty=tid>>4;
    float acc[4][4];
    #pragma unroll
    for(int i=0;i<4;i++)
        #pragma unroll
        for(int j=0;j<4;j++) acc[i][j]=0.f;
    for(int k0=0;k0<IIN;k0+=32){
        #pragma unroll
        for(int i=0;i<2;i++){
            int f=tid+i*256, row=f>>3, kq=(f&7)<<2;
            float4 v=*reinterpret_cast<const float4*>(x+(size_t)(m0+row)*IIN+k0+kq);
            As[kq][row]=v.x;As[kq+1][row]=v.y;As[kq+2][row]=v.z;As[kq+3][row]=v.w;
            float4 w=*reinterpret_cast<const float4*>(W_ih+(size_t)(n0+row)*(IIN+EEMB)+k0+kq);
            Bs[kq][row]=w.x;Bs[kq+1][row]=w.y;Bs[kq+2][row]=w.z;Bs[kq+3][row]=w.w;
        }
        __syncthreads();
        #pragma unroll
        for(int k=0;k<32;k++){
            float4 a=*reinterpret_cast<const float4*>(&As[k][ty*4]);
            float4 b=*reinterpret_cast<const float4*>(&Bs[k][tx*4]);
            float av[4]={a.x,a.y,a.z,a.w}, bv[4]={b.x,b.y,b.z,b.w};
            #pragma unroll
            for(int i=0;i<4;i++)
                #pragma unroll
                for(int j=0;j<4;j++) acc[i][j]=fmaf(av[i],bv[j],acc[i][j]);
        }
        __syncthreads();
    }
    #pragma unroll
    for(int i=0;i<4;i++){
        float4 v=make_float4(acc[i][0],acc[i][1],acc[i][2],acc[i][3]);
        *reinterpret_cast<float4*>(out+(size_t)(m0+ty*4+i)*HHID+n0+tx*4)=v;
    }
}

// write one bf16 element (row b, col h) of plane pair into fragment layout, slot 0
__device__ __forceinline__ void seed_elem(int chain,int b,int h,float val){
    int mt=b>>4, g=b&7, rp=(b>>3)&1;
    int ks=h>>4, rem=h&15, sl=rem>>3, qi=(rem&7)>>1, p=rem&1;
    int off=(mt*1024+ks*32+(g*4+qi))*16 + sl*8 + rp*4 + p*2;
    __nv_bfloat16 hi=__float2bfloat16_rn(val);
    __nv_bfloat16 lo=__float2bfloat16_rn(val-__bfloat162float(hi));
    *(__nv_bfloat16*)((char*)g_F1[chain][0]+off)=hi;
    *(__nv_bfloat16*)((char*)g_F2[chain][0]+off)=lo;
}

// ---- boot: h[0]=tanh(P0+m0@Wm^T+b_ih); seed fragment slot0; reset flags ----
__global__ __launch_bounds__(64) void boot_kernel(
    const float* __restrict__ h0,const float* __restrict__ m0,
    const float* __restrict__ W_ih,const float* __restrict__ b_ih,
    float* __restrict__ out){
    __shared__ float wm[EEMB];
    int h=blockIdx.x, b=threadIdx.x;
    if(h==0){
        if(b<16) g_flag[0][b*32]=0;
        else if(b<32) g_flag[1][(b-16)*32]=0;
    }
    for(int e=b;e<EEMB;e+=64) wm[e]=W_ih[(size_t)h*(IIN+EEMB)+IIN+e];
    __syncthreads();
    float acc=b_ih[h];
    const float* mr=m0+(size_t)b*EEMB;
    #pragma unroll 4
    for(int e=0;e<EEMB;e++) acc=fmaf(wm[e],mr[e],acc);
    int idx=b*HHID+h;
    float v=tanhf(out[idx]+acc);
    out[idx]=v;
    seed_elem(0,b,h,v);          // chain0 h-state = h[0]
    seed_elem(1,b,h,h0[idx]);    // chain1 h-state = h_0
}

// ---- C: persistent recurrence; direct fragment LDG, no SMEM A ----
// 32 CTAs: chain=bid&1, cta=bid>>1 (16/chain), col0=cta*32.
// chain0: t=2i+2 (1023 it); chain1: t=2i+1 (1024 it).
__global__ void __launch_bounds__(256,1) rnn_rec(float* __restrict__ out){
    extern __shared__ char smc[];
    uint2* Bf1=(uint2*)smc;            // [ng(4)][ks(32)][lane(32)]
    uint2* Bf2=(uint2*)(smc+32768);
    const int tid=threadIdx.x, bid=blockIdx.x;
    const int lane=tid&31, wid=tid>>5;
    const int chain=bid&1, cta=bid>>1, col0=cta*32;
    const int mtile=wid&3, npair=wid>>2;
    const int g=lane>>2, qi=lane&3;
    const int r0=mtile*16+g;
    const int cb0=col0+npair*16+2*qi, cb1=cb0+8;

    // resident B fragments: Wc slice for 32 cols, hi+lo planes
    for(int idx=tid;idx<4096;idx+=256){
        int ng=idx>>10, rem=idx&1023, ks=rem>>5, ln=rem&31;
        int n=col0+ng*8+(ln>>2), k=ks*16+(ln&3)*2;
        const float* wr=g_Wc+(size_t)n*HHID+k;
        unsigned h0v,l0v,h1v,l1v;
        split2(wr[0],wr[1],h0v,l0v);
        split2(wr[8],wr[9],h1v,l1v);
        Bf1[idx]=make_uint2(h0v,h1v);
        Bf2[idx]=make_uint2(l0v,l1v);
    }
    const float b00=g_bvec[cb0], b01=g_bvec[cb0+1];
    const float b10=g_bvec[cb1], b11=g_bvec[cb1+1];
    const uint2* Bp1a=Bf1+(2*npair)*1024+lane;
    const uint2* Bp1b=Bf1+(2*npair+1)*1024+lane;
    const uint2* Bp2a=Bf2+(2*npair)*1024+lane;
    const uint2* Bp2b=Bf2+(2*npair+1)*1024+lane;
    const int fo=mtile*1024+lane;              // + ks*32
    const int ksP=cta*2+npair;
    const int widx=mtile*1024+ksP*32+lane;
    const int n_it=1023+chain;
    __syncthreads();

    for(int i=0;i<n_it;i++){
        int t=2*i+2-chain;
        int rs=i&1, ws=rs^1;
        const uint4* Fp1=g_F1[chain][rs];
        const uint4* Fp2=g_F2[chain][rs];
        // P loads early
        size_t oa0=(size_t)t*BH+(size_t)r0*HHID+cb0;
        size_t oa1=oa0+8*HHID;
        size_t ob0=(size_t)t*BH+(size_t)r0*HHID+cb1;
        size_t ob1=ob0+8*HHID;
        float2 pa0=__ldcg((const float2*)(out+oa0));
        float2 pa1=__ldcg((const float2*)(out+oa1));
        float2 pb0=__ldcg((const float2*)(out+ob0));
        float2 pb1=__ldcg((const float2*)(out+ob1));
        float a0=0.f,a1=0.f,a2=0.f,a3=0.f;     // ng0 accum
        float c0=0.f,c1=0.f,c2=0.f,c3=0.f;     // ng1 accum
        uint4 f1c=__ldcg(Fp1+fo), f2c=__ldcg(Fp2+fo);
        #pragma unroll
        for(int ks=0;ks<32;ks++){
            uint4 f1n,f2n;
            if(ks<31){ f1n=__ldcg(Fp1+fo+(ks+1)*32); f2n=__ldcg(Fp2+fo+(ks+1)*32); }
            uint2 w1a=Bp1a[ks*32], w2a=Bp2a[ks*32];
            uint2 w1b=Bp1b[ks*32], w2b=Bp2b[ks*32];
            mma4(a0,a1,a2,a3, f1c.x,f1c.y,f1c.z,f1c.w, w1a.x,w1a.y);
            mma4(a0,a1,a2,a3, f1c.x,f1c.y,f1c.z,f1c.w, w2a.x,w2a.y);
            mma4(a0,a1,a2,a3, f2c.x,f2c.y,f2c.z,f2c.w, w1a.x,w1a.y);
            mma4(c0,c1,c2,c3, f1c.x,f1c.y,f1c.z,f1c.w, w1b.x,w1b.y);
            mma4(c0,c1,c2,c3, f1c.x,f1c.y,f1c.z,f1c.w, w2b.x,w2b.y);
            mma4(c0,c1,c2,c3, f2c.x,f2c.y,f2c.z,f2c.w, w1b.x,w1b.y);
            f1c=f1n; f2c=f2n;
        }
        // epilogue
        float v00=tanhf(pa0.x+b00+a0), v01=tanhf(pa0.y+b01+a1);
        float v02=tanhf(pa1.x+b00+a2), v03=tanhf(pa1.y+b01+a3);
        float v10=tanhf(pb0.x+b10+c0), v11=tanhf(pb0.y+b11+c1);
        float v12=tanhf(pb1.x+b10+c2), v13=tanhf(pb1.y+b11+c3);
        *(float2*)(out+oa0)=make_float2(v00,v01);
        *(float2*)(out+oa1)=make_float2(v02,v03);
        *(float2*)(out+ob0)=make_float2(v10,v11);
        *(float2*)(out+ob1)=make_float2(v12,v13);
        uint4 H,L;
        split2(v00,v01,H.x,L.x); split2(v02,v03,H.y,L.y);
        split2(v10,v11,H.z,L.z); split2(v12,v13,H.w,L.w);
        g_F1[chain][ws][widx]=H;
        g_F2[chain][ws][widx]=L;
        // barrier: arrive + poll 16 flags
        __syncthreads();
        if(tid==0){ __threadfence(); st_flag(&g_flag[chain][cta*32],(unsigned)(i+1)); }
        if(wid==0){
            const unsigned* fp=&g_flag[chain][(lane&15)*32];
            unsigned v;
            do { v=ld_flag(fp); } while(!__all_sync(0xffffffffu, v>(unsigned)i));
        }
        __syncthreads();
    }
}

// ---- fin: m_T = h[2046]@We^T + b_e ; h_T = out[2047] ----
__global__ __launch_bounds__(256) void fin_kernel(
    const float* __restrict__ W_embed,const float* __restrict__ b_embed,
    float* __restrict__ out){
    __shared__ float hsr[HHID];
    int b=blockIdx.x, e=threadIdx.x;
    hsr[e]=out[(size_t)2046*BH+(size_t)b*HHID+e];
    hsr[e+256]=out[(size_t)2046*BH+(size_t)b*HHID+e+256];
    out[OUT_HT+(size_t)b*HHID+e]=out[(size_t)2047*BH+(size_t)b*HHID+e];
    out[OUT_HT+(size_t)b*HHID+e+256]=out[(size_t)2047*BH+(size_t)b*HHID+e+256];
    __syncthreads();
    float acc=b_embed[e];
    const float* we=W_embed+(size_t)e*HHID;
    #pragma unroll 4
    for(int h=0;h<HHID;h++) acc=fmaf(hsr[h],we[h],acc);
    out[OUT_MT+(size_t)b*EEMB+e]=acc;
}

extern "C" void kernel_launch(void* const* d_in,const int* in_sizes,int n_in,
                              void* d_out,int out_size){
    const float* input_seq=(const float*)d_in[0];
    const float* h_0=(const float*)d_in[1];
    const float* m_0=(const float*)d_in[2];
    const float* W_embed=(const float*)d_in[3];
    const float* b_embed=(const float*)d_in[4];
    const float* W_ih=(const float*)d_in[5];
    const float* b_ih=(const float*)d_in[6];
    float* out=(float*)d_out;

    cudaFuncSetAttribute(rnn_rec,cudaFuncAttributeMaxDynamicSharedMemorySize,REC_SMEM);
    prep_kernel<<<HHID,256>>>(W_ih,W_embed,b_ih,b_embed);
    gemm_p_kernel<<<dim3(8,2048),256>>>(input_seq,W_ih,out);
    boot_kernel<<<HHID,64>>>(h_0,m_0,W_ih,b_ih,out);
    rnn_rec<<<32,256,REC_SMEM>>>(out);
    fin_kernel<<<BB,256>>>(W_embed,b_embed,out);
}